// round 7
// baseline (speedup 1.0000x reference)
#include <cuda_runtime.h>
#include <cuda_bf16.h>
#include <math.h>
#include <stdint.h>

// ---------------------------------------------------------------------------
// SwinTransformerBlock: B=4, H=W=192, C=256, HEADS=8, HD=32, WIN=8, SHIFT=4,
// HID=1024.  M = 4*192*192 = 147456 token rows.
// ---------------------------------------------------------------------------
#define MTOK   147456
#define NWIN   2304
#define HIDD   1024

typedef __nv_bfloat16 bf16;

// -------------------- scratch (device globals; no allocation) --------------
__device__ bf16  g_hln [MTOK * 256];
__device__ bf16  g_qkv [MTOK * 768];
__device__ bf16  g_attn[MTOK * 256];
__device__ float g_x1  [MTOK * 256];
__device__ bf16  g_ln2 [MTOK * 256];
__device__ bf16  g_m1  [MTOK * 1024];
__device__ bf16  g_wqkv[256 * 768];
__device__ bf16  g_wproj[256 * 256];
__device__ bf16  g_wfc1[256 * 1024];
__device__ bf16  g_wfc2[1024 * 256];

// ---------------------------------------------------------------------------
// One launch converting all four weight matrices fp32 -> bf16 ([K,N] layout).
// float4 counts: qkv 49152 | proj 16384 | fc1 65536 | fc2 65536  (tot 196608)
// ---------------------------------------------------------------------------
__global__ __launch_bounds__(256) void cvt_all(const float* __restrict__ w0,
                                               const float* __restrict__ w1,
                                               const float* __restrict__ w2,
                                               const float* __restrict__ w3,
                                               bf16* d0, bf16* d1, bf16* d2, bf16* d3) {
    int i = blockIdx.x * 256 + threadIdx.x;
    const float* s; bf16* d; int off;
    if (i < 49152)       { s = w0; d = d0; off = i; }
    else if (i < 65536)  { s = w1; d = d1; off = i - 49152; }
    else if (i < 131072) { s = w2; d = d2; off = i - 65536; }
    else                 { s = w3; d = d3; off = i - 131072; }
    float4 v = ((const float4*)s)[off];
    bf16 o[4] = {__float2bfloat16_rn(v.x), __float2bfloat16_rn(v.y),
                 __float2bfloat16_rn(v.z), __float2bfloat16_rn(v.w)};
    *(uint64_t*)(d + off * 4) = *(uint64_t*)o;
}

// ---------------------------------------------------------------------------
// LayerNorm, warp per token, bf16 output.  GATHER=true applies cyclic shift +
// window reorder (dst is window-token order).
// ---------------------------------------------------------------------------
template<bool GATHER>
__global__ __launch_bounds__(256) void ln_kernel(const float* __restrict__ x,
                                                 const float* __restrict__ g,
                                                 const float* __restrict__ bb,
                                                 bf16* __restrict__ out) {
    int warp = (blockIdx.x * 256 + threadIdx.x) >> 5;
    int lane = threadIdx.x & 31;
    int src;
    if (GATHER) {
        int w = warp >> 6, t = warp & 63;
        int b = w / 576, rem = w - b * 576;
        int wh = rem / 24, ww = rem - wh * 24;
        int r = (wh << 3) + (t >> 3) + 4; if (r >= 192) r -= 192;
        int c = (ww << 3) + (t & 7) + 4;  if (c >= 192) c -= 192;
        src = (b * 192 + r) * 192 + c;
    } else {
        src = warp;
    }
    const float4* xp = (const float4*)x + (size_t)src * 64 + lane * 2;
    float4 v0 = xp[0], v1 = xp[1];
    float s = v0.x + v0.y + v0.z + v0.w + v1.x + v1.y + v1.z + v1.w;
#pragma unroll
    for (int o = 16; o; o >>= 1) s += __shfl_xor_sync(0xffffffffu, s, o);
    float mean = s * (1.0f / 256.0f);
    float q =
        (v0.x - mean) * (v0.x - mean) + (v0.y - mean) * (v0.y - mean) +
        (v0.z - mean) * (v0.z - mean) + (v0.w - mean) * (v0.w - mean) +
        (v1.x - mean) * (v1.x - mean) + (v1.y - mean) * (v1.y - mean) +
        (v1.z - mean) * (v1.z - mean) + (v1.w - mean) * (v1.w - mean);
#pragma unroll
    for (int o = 16; o; o >>= 1) q += __shfl_xor_sync(0xffffffffu, q, o);
    float inv = rsqrtf(q * (1.0f / 256.0f) + 1e-5f);

    const float4* gp = (const float4*)g  + lane * 2;
    const float4* bp = (const float4*)bb + lane * 2;
    float4 g0 = gp[0], g1 = gp[1], b0 = bp[0], b1 = bp[1];
    bf16 o8[8];
    o8[0] = __float2bfloat16_rn((v0.x - mean) * inv * g0.x + b0.x);
    o8[1] = __float2bfloat16_rn((v0.y - mean) * inv * g0.y + b0.y);
    o8[2] = __float2bfloat16_rn((v0.z - mean) * inv * g0.z + b0.z);
    o8[3] = __float2bfloat16_rn((v0.w - mean) * inv * g0.w + b0.w);
    o8[4] = __float2bfloat16_rn((v1.x - mean) * inv * g1.x + b1.x);
    o8[5] = __float2bfloat16_rn((v1.y - mean) * inv * g1.y + b1.y);
    o8[6] = __float2bfloat16_rn((v1.z - mean) * inv * g1.z + b1.z);
    o8[7] = __float2bfloat16_rn((v1.w - mean) * inv * g1.w + b1.w);
    *(uint4*)(out + (size_t)warp * 256 + lane * 8) = *(uint4*)o8;
}

// ---------------------------------------------------------------------------
// primitives
// ---------------------------------------------------------------------------
__device__ __forceinline__ void ldsm_x4(uint32_t a, uint32_t& r0, uint32_t& r1,
                                        uint32_t& r2, uint32_t& r3) {
    asm volatile("ldmatrix.sync.aligned.m8n8.x4.shared.b16 {%0,%1,%2,%3}, [%4];\n"
                 : "=r"(r0), "=r"(r1), "=r"(r2), "=r"(r3) : "r"(a));
}
__device__ __forceinline__ void ldsm_x4t(uint32_t a, uint32_t& r0, uint32_t& r1,
                                         uint32_t& r2, uint32_t& r3) {
    asm volatile("ldmatrix.sync.aligned.m8n8.x4.trans.shared.b16 {%0,%1,%2,%3}, [%4];\n"
                 : "=r"(r0), "=r"(r1), "=r"(r2), "=r"(r3) : "r"(a));
}
__device__ __forceinline__ void mma_bf16(float* c, const uint32_t* a, const uint32_t* b) {
    asm volatile("mma.sync.aligned.m16n8k16.row.col.f32.bf16.bf16.f32 "
                 "{%0,%1,%2,%3}, {%4,%5,%6,%7}, {%8,%9}, {%0,%1,%2,%3};\n"
                 : "+f"(c[0]), "+f"(c[1]), "+f"(c[2]), "+f"(c[3])
                 : "r"(a[0]), "r"(a[1]), "r"(a[2]), "r"(a[3]), "r"(b[0]), "r"(b[1]));
}
__device__ __forceinline__ void cpasync16(uint32_t dst, const void* src) {
    asm volatile("cp.async.ca.shared.global [%0], [%1], 16;\n" :: "r"(dst), "l"(src));
}
#define SWZ(o) ((o) ^ (((o) >> 3) & 0x70))

// window-token row -> flat token index (inverse shift + un-window)
__device__ __forceinline__ int wtok2tok(int row) {
    int w = row >> 6, t = row & 63;
    int b = w / 576, rem = w - b * 576;
    int wh = rem / 24, ww = rem - wh * 24;
    int r = (wh << 3) + (t >> 3) + 4; if (r >= 192) r -= 192;
    int c = (ww << 3) + (t & 7) + 4;  if (c >= 192) c -= 192;
    return (b * 192 + r) * 192 + c;
}

// ---------------------------------------------------------------------------
// bf16 HMMA GEMM, 3-stage cp.async multistage pipeline, single barrier/step.
// BM=BN=128, BK=64, 256 threads, warp computes 64x32 via 4x4 m16n8k16.
// A staged in SW128-swizzled 128B rows (no pad); B padded stride 136.
// OP: 0 = none, 1 = exact GELU.  SCAT: window->token scatter + residual.
// ---------------------------------------------------------------------------
#define ASTG 16384            // 128 rows * 128 B
#define BNS  136
#define BSTG (64 * BNS * 2)   // 17408
#define GSMEM (3 * (ASTG + BSTG) + 128)

template<int OP, bool RES, bool SCAT, typename OutT>
__global__ __launch_bounds__(256, 2) void bgemm(const bf16* __restrict__ A,
                                                const bf16* __restrict__ Bw,
                                                const float* __restrict__ bias,
                                                const float* __restrict__ res,
                                                OutT* __restrict__ C,
                                                int M, int N, int K) {
    extern __shared__ char smraw[];
    uint32_t sb = (uint32_t)__cvta_generic_to_shared(smraw);
    sb = (sb + 127) & ~127u;
    int tid = threadIdx.x;
    int lane = tid & 31, wid = tid >> 5;
    int bm = blockIdx.x * 128;
    int bn = blockIdx.y * 128;
    int m_base = (wid & 1) * 64;
    int n_base = (wid >> 1) * 32;
    int nsteps = K >> 6;

    // per-thread load geometry
    int arow = tid >> 3, ach = tid & 7;     // + 32*l rows
    int brow = tid >> 4, bch = tid & 15;    // + 16*l rows
    const bf16* ag[4]; const bf16* bg[4];
    uint32_t aof[4], bof[4];
#pragma unroll
    for (int l = 0; l < 4; l++) {
        ag[l] = A + (size_t)(bm + arow + 32 * l) * K + ach * 8;
        bg[l] = Bw + (size_t)(brow + 16 * l) * N + bn + bch * 8;
        aof[l] = SWZ((arow + 32 * l) * 128 + ach * 16);
        bof[l] = ((brow + 16 * l) * BNS + bch * 8) * 2;
    }

    // prologue: stages 0,1
#pragma unroll
    for (int p = 0; p < 2; p++) {
        uint32_t da = sb + p * ASTG, db = sb + 3 * ASTG + p * BSTG;
#pragma unroll
        for (int l = 0; l < 4; l++) {
            cpasync16(da + aof[l], ag[l] + p * 64);
            cpasync16(db + bof[l], bg[l] + (size_t)p * 64 * N);
        }
        asm volatile("cp.async.commit_group;");
    }

    float acc[4][4][4] = {};
    int s = 0;
    for (int j = 0; j < nsteps; j++) {
        asm volatile("cp.async.wait_group 1;");
        __syncthreads();
        if (j + 2 < nsteps) {
            int ns = (s + 2 >= 3) ? s - 1 : s + 2;
            uint32_t da = sb + ns * ASTG, db = sb + 3 * ASTG + ns * BSTG;
#pragma unroll
            for (int l = 0; l < 4; l++) {
                cpasync16(da + aof[l], ag[l] + (j + 2) * 64);
                cpasync16(db + bof[l], bg[l] + (size_t)(j + 2) * 64 * N);
            }
        }
        asm volatile("cp.async.commit_group;");

        uint32_t da = sb + s * ASTG, db = sb + 3 * ASTG + s * BSTG;
#pragma unroll
        for (int kk = 0; kk < 4; kk++) {
            uint32_t af[4][4], bfr[4][2];
#pragma unroll
            for (int i = 0; i < 4; i++) {
                int row = m_base + i * 16 + (lane & 15);
                uint32_t off = SWZ(row * 128 + kk * 32 + ((lane & 16) ? 16 : 0));
                ldsm_x4(da + off, af[i][0], af[i][1], af[i][2], af[i][3]);
            }
#pragma unroll
            for (int ng = 0; ng < 2; ng++) {
                int row = kk * 16 + (lane & 15);
                int col = n_base + ng * 16 + ((lane & 16) ? 8 : 0);
                uint32_t r0, r1, r2, r3;
                ldsm_x4t(db + (row * BNS + col) * 2, r0, r1, r2, r3);
                bfr[ng * 2][0] = r0; bfr[ng * 2][1] = r1;
                bfr[ng * 2 + 1][0] = r2; bfr[ng * 2 + 1][1] = r3;
            }
#pragma unroll
            for (int i = 0; i < 4; i++)
#pragma unroll
                for (int jn = 0; jn < 4; jn++) mma_bf16(acc[i][jn], af[i], bfr[jn]);
        }
        s++; if (s == 3) s = 0;
    }

    // epilogue
    int r = lane >> 2, c2 = (lane & 3) * 2;
#pragma unroll
    for (int i = 0; i < 4; i++) {
#pragma unroll
        for (int j = 0; j < 4; j++) {
            int col = bn + n_base + j * 8 + c2;
            float b0 = bias[col], b1 = bias[col + 1];
#pragma unroll
            for (int h = 0; h < 2; h++) {
                int row = bm + m_base + i * 16 + r + h * 8;
                float v0 = acc[i][j][h * 2 + 0] + b0;
                float v1 = acc[i][j][h * 2 + 1] + b1;
                if (OP == 1) {
                    v0 = 0.5f * v0 * (1.0f + erff(v0 * 0.70710678118654752f));
                    v1 = 0.5f * v1 * (1.0f + erff(v1 * 0.70710678118654752f));
                }
                int orow = row;
                if (SCAT) orow = wtok2tok(row);
                if (RES || SCAT) {
                    float2 rr = *(const float2*)(res + (size_t)orow * N + col);
                    v0 += rr.x; v1 += rr.y;
                }
                if (sizeof(OutT) == 4) {
                    float2 o = {v0, v1};
                    *(float2*)((float*)C + (size_t)orow * N + col) = o;
                } else {
                    __nv_bfloat162 o;
                    o.x = __float2bfloat16_rn(v0); o.y = __float2bfloat16_rn(v1);
                    *(__nv_bfloat162*)((bf16*)C + (size_t)orow * N + col) = o;
                }
            }
        }
    }
}

// ---------------------------------------------------------------------------
// Tensor-core window attention.  One block per window: 512 threads, 16 warps;
// warp w handles head w/2, q-rows (w&1)*32..+31.
// ---------------------------------------------------------------------------
#define QS 776
#define ATTN_SMEM (64 * QS * 2 + 1800 * 4)

__global__ __launch_bounds__(512) void attn_mma_kernel(const bf16* __restrict__ qkv,
                                                       const float* __restrict__ bias_table,
                                                       bf16* __restrict__ attno) {
    extern __shared__ char smem_raw[];
    bf16*  sq  = (bf16*)smem_raw;
    float* sbt = (float*)(smem_raw + 64 * QS * 2);
    int tid = threadIdx.x;
    int w = blockIdx.x;

    const uint4* gsrc = (const uint4*)(qkv + (size_t)w * 64 * 768);
#pragma unroll
    for (int l = 0; l < 12; l++) {
        int idx = tid + l * 512;
        int row = idx / 96, c8 = idx - row * 96;
        *(uint4*)(sq + row * QS + c8 * 8) = gsrc[row * 96 + c8];
    }
    for (int i = tid; i < 1800; i += 512) {
        int h = i / 225, rr = i - h * 225;
        sbt[i] = bias_table[rr * 8 + h];
    }
    __syncthreads();

    int lane = tid & 31, wid = tid >> 5;
    int head = wid >> 1, qr0 = (wid & 1) * 32;
    uint32_t sbase = (uint32_t)__cvta_generic_to_shared(sq);
    int qcol = head * 32, kcol = 256 + head * 32, vcol = 512 + head * 32;

    float s[2][8][4] = {};
#pragma unroll
    for (int ks = 0; ks < 2; ks++) {
        uint32_t aq[2][4];
#pragma unroll
        for (int mt = 0; mt < 2; mt++) {
            int row = qr0 + mt * 16 + (lane & 15);
            int col = qcol + ks * 16 + ((lane & 16) ? 8 : 0);
            ldsm_x4(sbase + (row * QS + col) * 2, aq[mt][0], aq[mt][1], aq[mt][2], aq[mt][3]);
        }
        uint32_t bk[8][2];
#pragma unroll
        for (int tg = 0; tg < 4; tg++) {
            int row = tg * 16 + (lane & 15);
            int col = kcol + ks * 16 + ((lane & 16) ? 8 : 0);
            uint32_t m0, m1, m2, m3;
            ldsm_x4(sbase + (row * QS + col) * 2, m0, m1, m2, m3);
            bk[tg * 2][0] = m0; bk[tg * 2][1] = m2;
            bk[tg * 2 + 1][0] = m1; bk[tg * 2 + 1][1] = m3;
        }
#pragma unroll
        for (int mt = 0; mt < 2; mt++)
#pragma unroll
            for (int j = 0; j < 8; j++) mma_bf16(s[mt][j], aq[mt], bk[j]);
    }

    const float scale = 0.17677669529663687f;
    const float* bt = sbt + head * 225;
#pragma unroll
    for (int mt = 0; mt < 2; mt++)
#pragma unroll
        for (int j = 0; j < 8; j++)
#pragma unroll
            for (int e = 0; e < 4; e++) {
                int qi = qr0 + mt * 16 + (lane >> 2) + ((e >> 1) << 3);
                int kj = j * 8 + ((lane & 3) << 1) + (e & 1);
                int ridx = ((qi >> 3) - (kj >> 3) + 7) * 15 + (qi & 7) - (kj & 7) + 7;
                s[mt][j][e] = s[mt][j][e] * scale + bt[ridx];
            }

#pragma unroll
    for (int mt = 0; mt < 2; mt++)
#pragma unroll
        for (int h = 0; h < 2; h++) {
            float mx = -1e30f;
#pragma unroll
            for (int j = 0; j < 8; j++)
                mx = fmaxf(mx, fmaxf(s[mt][j][h * 2], s[mt][j][h * 2 + 1]));
            mx = fmaxf(mx, __shfl_xor_sync(0xffffffffu, mx, 1));
            mx = fmaxf(mx, __shfl_xor_sync(0xffffffffu, mx, 2));
            float sum = 0.0f;
#pragma unroll
            for (int j = 0; j < 8; j++) {
                float e0 = __expf(s[mt][j][h * 2] - mx);
                float e1 = __expf(s[mt][j][h * 2 + 1] - mx);
                s[mt][j][h * 2] = e0; s[mt][j][h * 2 + 1] = e1;
                sum += e0 + e1;
            }
            sum += __shfl_xor_sync(0xffffffffu, sum, 1);
            sum += __shfl_xor_sync(0xffffffffu, sum, 2);
            float rn = 1.0f / sum;
#pragma unroll
            for (int j = 0; j < 8; j++) { s[mt][j][h * 2] *= rn; s[mt][j][h * 2 + 1] *= rn; }
        }

    uint32_t ap[2][4][4];
#pragma unroll
    for (int mt = 0; mt < 2; mt++)
#pragma unroll
        for (int kt = 0; kt < 4; kt++) {
            __nv_bfloat162 t;
            t = __floats2bfloat162_rn(s[mt][2 * kt][0], s[mt][2 * kt][1]);         ap[mt][kt][0] = *(uint32_t*)&t;
            t = __floats2bfloat162_rn(s[mt][2 * kt][2], s[mt][2 * kt][3]);         ap[mt][kt][1] = *(uint32_t*)&t;
            t = __floats2bfloat162_rn(s[mt][2 * kt + 1][0], s[mt][2 * kt + 1][1]); ap[mt][kt][2] = *(uint32_t*)&t;
            t = __floats2bfloat162_rn(s[mt][2 * kt + 1][2], s[mt][2 * kt + 1][3]); ap[mt][kt][3] = *(uint32_t*)&t;
        }

    float o[2][4][4] = {};
#pragma unroll
    for (int kt = 0; kt < 4; kt++) {
        uint32_t bv[4][2];
#pragma unroll
        for (int ng = 0; ng < 2; ng++) {
            int row = kt * 16 + (lane & 15);
            int col = vcol + ng * 16 + ((lane & 16) ? 8 : 0);
            uint32_t r0, r1, r2, r3;
            ldsm_x4t(sbase + (row * QS + col) * 2, r0, r1, r2, r3);
            bv[ng * 2][0] = r0; bv[ng * 2][1] = r1;
            bv[ng * 2 + 1][0] = r2; bv[ng * 2 + 1][1] = r3;
        }
#pragma unroll
        for (int mt = 0; mt < 2; mt++)
#pragma unroll
            for (int nt = 0; nt < 4; nt++) mma_bf16(o[mt][nt], ap[mt][kt], bv[nt]);
    }

#pragma unroll
    for (int mt = 0; mt < 2; mt++)
#pragma unroll
        for (int nt = 0; nt < 4; nt++)
#pragma unroll
            for (int h = 0; h < 2; h++) {
                int row = qr0 + mt * 16 + (lane >> 2) + h * 8;
                int col = head * 32 + nt * 8 + ((lane & 3) << 1);
                __nv_bfloat162 t = __floats2bfloat162_rn(o[mt][nt][h * 2], o[mt][nt][h * 2 + 1]);
                *(__nv_bfloat162*)(attno + (size_t)(w * 64 + row) * 256 + col) = t;
            }
}

// ---------------------------------------------------------------------------
extern "C" void kernel_launch(void* const* d_in, const int* in_sizes, int n_in,
                              void* d_out, int out_size) {
    const float* x         = (const float*)d_in[0];
    const float* n1g       = (const float*)d_in[1];
    const float* n1b       = (const float*)d_in[2];
    const float* qkv_w     = (const float*)d_in[3];
    const float* qkv_b     = (const float*)d_in[4];
    const float* bias_tab  = (const float*)d_in[5];
    const float* proj_w    = (const float*)d_in[6];
    const float* proj_b    = (const float*)d_in[7];
    const float* n2g       = (const float*)d_in[8];
    const float* n2b       = (const float*)d_in[9];
    const float* fc1_w     = (const float*)d_in[10];
    const float* fc1_b     = (const float*)d_in[11];
    const float* fc2_w     = (const float*)d_in[12];
    const float* fc2_b     = (const float*)d_in[13];
    float* out = (float*)d_out;

    void *pHln, *pQkv, *pAttn, *pX1, *pLn2, *pM1, *pWq, *pWp, *pW1, *pW2;
    cudaGetSymbolAddress(&pHln,  g_hln);
    cudaGetSymbolAddress(&pQkv,  g_qkv);
    cudaGetSymbolAddress(&pAttn, g_attn);
    cudaGetSymbolAddress(&pX1,   g_x1);
    cudaGetSymbolAddress(&pLn2,  g_ln2);
    cudaGetSymbolAddress(&pM1,   g_m1);
    cudaGetSymbolAddress(&pWq,   g_wqkv);
    cudaGetSymbolAddress(&pWp,   g_wproj);
    cudaGetSymbolAddress(&pW1,   g_wfc1);
    cudaGetSymbolAddress(&pW2,   g_wfc2);
    bf16* hln  = (bf16*)pHln;  bf16* qkv  = (bf16*)pQkv;
    bf16* attn = (bf16*)pAttn; float* x1  = (float*)pX1;
    bf16* ln2  = (bf16*)pLn2;  bf16* m1   = (bf16*)pM1;
    bf16* wq = (bf16*)pWq; bf16* wp = (bf16*)pWp;
    bf16* w1 = (bf16*)pW1; bf16* w2 = (bf16*)pW2;

    static int attr_set = 0;
    if (!attr_set) {
        cudaFuncSetAttribute(attn_mma_kernel,
                             cudaFuncAttributeMaxDynamicSharedMemorySize, ATTN_SMEM);
        cudaFuncSetAttribute(bgemm<0, false, false, bf16>,
                             cudaFuncAttributeMaxDynamicSharedMemorySize, GSMEM);
        cudaFuncSetAttribute(bgemm<0, false, true, float>,
                             cudaFuncAttributeMaxDynamicSharedMemorySize, GSMEM);
        cudaFuncSetAttribute(bgemm<1, false, false, bf16>,
                             cudaFuncAttributeMaxDynamicSharedMemorySize, GSMEM);
        cudaFuncSetAttribute(bgemm<0, true, false, float>,
                             cudaFuncAttributeMaxDynamicSharedMemorySize, GSMEM);
        attr_set = 1;
    }

    // 0. weight conversion (single launch, [K,N] bf16)
    cvt_all<<<768, 256>>>(qkv_w, proj_w, fc1_w, fc2_w, wq, wp, w1, w2);
    // 1. LN1 + shift + windowing -> hln (bf16, window-token order)
    ln_kernel<true><<<MTOK / 8, 256>>>(x, n1g, n1b, hln);
    // 2. qkv GEMM (bf16 out)
    bgemm<0, false, false, bf16><<<dim3(MTOK / 128, 6), 256, GSMEM>>>(
        hln, wq, qkv_b, nullptr, qkv, MTOK, 768, 256);
    // 3. tensor-core window attention -> attn (bf16)
    attn_mma_kernel<<<NWIN, 512, ATTN_SMEM>>>(qkv, bias_tab, attn);
    // 4. proj GEMM + un-window scatter + residual -> x1 (fp32, token order)
    bgemm<0, false, true, float><<<dim3(MTOK / 128, 2), 256, GSMEM>>>(
        attn, wp, proj_b, x, x1, MTOK, 256, 256);
    // 5. LN2 -> ln2 (bf16)
    ln_kernel<false><<<MTOK / 8, 256>>>(x1, n2g, n2b, ln2);
    // 6. fc1 + GELU -> m1 (bf16)
    bgemm<1, false, false, bf16><<<dim3(MTOK / 128, 8), 256, GSMEM>>>(
        ln2, w1, fc1_b, nullptr, m1, MTOK, 1024, 256);
    // 7. fc2 + residual -> out (fp32)
    bgemm<0, true, false, float><<<dim3(MTOK / 128, 2), 256, GSMEM>>>(
        m1, w2, fc2_b, x1, out, MTOK, 256, 1024);
}

// round 9
// speedup vs baseline: 1.2381x; 1.2381x over previous
#include <cuda_runtime.h>
#include <cuda_bf16.h>
#include <math.h>
#include <stdint.h>

// ---------------------------------------------------------------------------
// SwinTransformerBlock: B=4, H=W=192, C=256, HEADS=8, HD=32, WIN=8, SHIFT=4,
// HID=1024.  M = 4*192*192 = 147456 token rows.
// ---------------------------------------------------------------------------
#define MTOK   147456
#define NWIN   2304
#define HIDD   1024

typedef __nv_bfloat16 bf16;

// -------------------- scratch (device globals; no allocation) --------------
__device__ bf16  g_hln [MTOK * 256];
__device__ bf16  g_qkv [MTOK * 768];
__device__ bf16  g_attn[MTOK * 256];
__device__ float g_x1  [MTOK * 256];
__device__ bf16  g_ln2 [MTOK * 256];
__device__ bf16  g_m1  [MTOK * 1024];
__device__ bf16  g_wqkv[256 * 768];
__device__ bf16  g_wproj[256 * 256];
__device__ bf16  g_wfc1[256 * 1024];
__device__ bf16  g_wfc2[1024 * 256];

// ---------------------------------------------------------------------------
// One launch converting all four weight matrices fp32 -> bf16 ([K,N] layout).
// ---------------------------------------------------------------------------
__global__ __launch_bounds__(256) void cvt_all(const float* __restrict__ w0,
                                               const float* __restrict__ w1,
                                               const float* __restrict__ w2,
                                               const float* __restrict__ w3,
                                               bf16* d0, bf16* d1, bf16* d2, bf16* d3) {
    int i = blockIdx.x * 256 + threadIdx.x;
    const float* s; bf16* d; int off;
    if (i < 49152)       { s = w0; d = d0; off = i; }
    else if (i < 65536)  { s = w1; d = d1; off = i - 49152; }
    else if (i < 131072) { s = w2; d = d2; off = i - 65536; }
    else                 { s = w3; d = d3; off = i - 131072; }
    float4 v = ((const float4*)s)[off];
    bf16 o[4] = {__float2bfloat16_rn(v.x), __float2bfloat16_rn(v.y),
                 __float2bfloat16_rn(v.z), __float2bfloat16_rn(v.w)};
    *(uint64_t*)(d + off * 4) = *(uint64_t*)o;
}

// ---------------------------------------------------------------------------
// LayerNorm, warp per token, bf16 output.  GATHER=true applies cyclic shift +
// window reorder (dst is window-token order).
// ---------------------------------------------------------------------------
template<bool GATHER>
__global__ __launch_bounds__(256) void ln_kernel(const float* __restrict__ x,
                                                 const float* __restrict__ g,
                                                 const float* __restrict__ bb,
                                                 bf16* __restrict__ out) {
    int warp = (blockIdx.x * 256 + threadIdx.x) >> 5;
    int lane = threadIdx.x & 31;
    int src;
    if (GATHER) {
        int w = warp >> 6, t = warp & 63;
        int b = w / 576, rem = w - b * 576;
        int wh = rem / 24, ww = rem - wh * 24;
        int r = (wh << 3) + (t >> 3) + 4; if (r >= 192) r -= 192;
        int c = (ww << 3) + (t & 7) + 4;  if (c >= 192) c -= 192;
        src = (b * 192 + r) * 192 + c;
    } else {
        src = warp;
    }
    const float4* xp = (const float4*)x + (size_t)src * 64 + lane * 2;
    float4 v0 = xp[0], v1 = xp[1];
    float s = v0.x + v0.y + v0.z + v0.w + v1.x + v1.y + v1.z + v1.w;
#pragma unroll
    for (int o = 16; o; o >>= 1) s += __shfl_xor_sync(0xffffffffu, s, o);
    float mean = s * (1.0f / 256.0f);
    float q =
        (v0.x - mean) * (v0.x - mean) + (v0.y - mean) * (v0.y - mean) +
        (v0.z - mean) * (v0.z - mean) + (v0.w - mean) * (v0.w - mean) +
        (v1.x - mean) * (v1.x - mean) + (v1.y - mean) * (v1.y - mean) +
        (v1.z - mean) * (v1.z - mean) + (v1.w - mean) * (v1.w - mean);
#pragma unroll
    for (int o = 16; o; o >>= 1) q += __shfl_xor_sync(0xffffffffu, q, o);
    float inv = rsqrtf(q * (1.0f / 256.0f) + 1e-5f);

    const float4* gp = (const float4*)g  + lane * 2;
    const float4* bp = (const float4*)bb + lane * 2;
    float4 g0 = gp[0], g1 = gp[1], b0 = bp[0], b1 = bp[1];
    bf16 o8[8];
    o8[0] = __float2bfloat16_rn((v0.x - mean) * inv * g0.x + b0.x);
    o8[1] = __float2bfloat16_rn((v0.y - mean) * inv * g0.y + b0.y);
    o8[2] = __float2bfloat16_rn((v0.z - mean) * inv * g0.z + b0.z);
    o8[3] = __float2bfloat16_rn((v0.w - mean) * inv * g0.w + b0.w);
    o8[4] = __float2bfloat16_rn((v1.x - mean) * inv * g1.x + b1.x);
    o8[5] = __float2bfloat16_rn((v1.y - mean) * inv * g1.y + b1.y);
    o8[6] = __float2bfloat16_rn((v1.z - mean) * inv * g1.z + b1.z);
    o8[7] = __float2bfloat16_rn((v1.w - mean) * inv * g1.w + b1.w);
    *(uint4*)(out + (size_t)warp * 256 + lane * 8) = *(uint4*)o8;
}

// ---------------------------------------------------------------------------
// primitives
// ---------------------------------------------------------------------------
__device__ __forceinline__ void ldsm_x4(uint32_t a, uint32_t& r0, uint32_t& r1,
                                        uint32_t& r2, uint32_t& r3) {
    asm volatile("ldmatrix.sync.aligned.m8n8.x4.shared.b16 {%0,%1,%2,%3}, [%4];\n"
                 : "=r"(r0), "=r"(r1), "=r"(r2), "=r"(r3) : "r"(a));
}
__device__ __forceinline__ void ldsm_x4t(uint32_t a, uint32_t& r0, uint32_t& r1,
                                         uint32_t& r2, uint32_t& r3) {
    asm volatile("ldmatrix.sync.aligned.m8n8.x4.trans.shared.b16 {%0,%1,%2,%3}, [%4];\n"
                 : "=r"(r0), "=r"(r1), "=r"(r2), "=r"(r3) : "r"(a));
}
__device__ __forceinline__ void mma_bf16(float* c, const uint32_t* a, const uint32_t* b) {
    asm volatile("mma.sync.aligned.m16n8k16.row.col.f32.bf16.bf16.f32 "
                 "{%0,%1,%2,%3}, {%4,%5,%6,%7}, {%8,%9}, {%0,%1,%2,%3};\n"
                 : "+f"(c[0]), "+f"(c[1]), "+f"(c[2]), "+f"(c[3])
                 : "r"(a[0]), "r"(a[1]), "r"(a[2]), "r"(a[3]), "r"(b[0]), "r"(b[1]));
}
__device__ __forceinline__ void cpasync16(uint32_t dst, const void* src) {
    asm volatile("cp.async.ca.shared.global [%0], [%1], 16;\n" :: "r"(dst), "l"(src));
}
__device__ __forceinline__ void cpcommit() {
    asm volatile("cp.async.commit_group;\n");
}

// window-token row -> flat token index (inverse shift + un-window)
__device__ __forceinline__ int wtok2tok(int row) {
    int w = row >> 6, t = row & 63;
    int b = w / 576, rem = w - b * 576;
    int wh = rem / 24, ww = rem - wh * 24;
    int r = (wh << 3) + (t >> 3) + 4; if (r >= 192) r -= 192;
    int c = (ww << 3) + (t & 7) + 4;  if (c >= 192) c -= 192;
    return (b * 192 + r) * 192 + c;
}

// ---------------------------------------------------------------------------
// bf16 tensor-core GEMM, cp.async 2-stage pipeline (R4 version, 1175us).
// BM=BN=128, BK=32, 256 threads, warp computes 64x32 via 4x4 m16n8k16 mma.
// OP: 0 = none, 1 = exact GELU.  SCAT: window->token scatter + residual.
// ---------------------------------------------------------------------------
#define AKS 40     // A smem row stride (bf16)
#define BNS 136    // B smem row stride (bf16)
#define ASZ (128 * AKS * 2)   // bytes per A stage
#define BSZ (32 * BNS * 2)    // bytes per B stage

template<int OP, bool RES, bool SCAT, typename OutT>
__global__ __launch_bounds__(256) void bgemm(const bf16* __restrict__ A,
                                             const bf16* __restrict__ Bw,
                                             const float* __restrict__ bias,
                                             const float* __restrict__ res,
                                             OutT* __restrict__ C,
                                             int M, int N, int K) {
    __shared__ bf16 As[2][128 * AKS];
    __shared__ bf16 Bs[2][32 * BNS];
    int tid = threadIdx.x;
    int lane = tid & 31, wid = tid >> 5;
    int bm = blockIdx.x * 128;
    int bn = blockIdx.y * 128;
    int m_base = (wid & 1) * 64;
    int n_base = (wid >> 1) * 32;

    int a_row0 = tid >> 2,        a_kc0 = (tid & 3) * 8;
    int a_row1 = (tid + 256) >> 2;
    int b_row0 = tid >> 4,        b_nc0 = (tid & 15) * 8;
    int b_row1 = (tid + 256) >> 4;

    const bf16* Ag0 = A + (size_t)(bm + a_row0) * K + a_kc0;
    const bf16* Ag1 = A + (size_t)(bm + a_row1) * K + a_kc0;
    const bf16* Bg0 = Bw + (size_t)b_row0 * N + bn + b_nc0;
    const bf16* Bg1 = Bw + (size_t)b_row1 * N + bn + b_nc0;

    uint32_t a_smem = (uint32_t)__cvta_generic_to_shared(&As[0][0]);
    uint32_t b_smem = (uint32_t)__cvta_generic_to_shared(&Bs[0][0]);
    uint32_t a_st0 = a_smem + (a_row0 * AKS + a_kc0) * 2;
    uint32_t a_st1 = a_smem + (a_row1 * AKS + a_kc0) * 2;
    uint32_t b_st0 = b_smem + (b_row0 * BNS + b_nc0) * 2;
    uint32_t b_st1 = b_smem + (b_row1 * BNS + b_nc0) * 2;

    int a_lrow = m_base + (lane & 15);
    int a_lcol = (lane & 16) ? 8 : 0;
    uint32_t a_addr = a_smem + (a_lrow * AKS + a_lcol) * 2;
    int b_lrow = (lane & 15);
    int b_lcol = n_base + ((lane & 16) ? 8 : 0);
    uint32_t b_addr = b_smem + (b_lrow * BNS + b_lcol) * 2;

    float acc[4][4][4] = {};
    int nsteps = K >> 5;

    cpasync16(a_st0, Ag0); cpasync16(a_st1, Ag1);
    cpasync16(b_st0, Bg0); cpasync16(b_st1, Bg1);
    cpcommit();

    for (int step = 0; step < nsteps; step++) {
        int buf = step & 1;
        if (step + 1 < nsteps) {
            int nb = buf ^ 1;
            cpasync16(a_st0 + nb * ASZ, Ag0 + (step + 1) * 32);
            cpasync16(a_st1 + nb * ASZ, Ag1 + (step + 1) * 32);
            cpasync16(b_st0 + nb * BSZ, Bg0 + (size_t)(step + 1) * 32 * N);
            cpasync16(b_st1 + nb * BSZ, Bg1 + (size_t)(step + 1) * 32 * N);
            cpcommit();
            asm volatile("cp.async.wait_group 1;\n");
        } else {
            asm volatile("cp.async.wait_group 0;\n");
        }
        __syncthreads();
        uint32_t ab = a_addr + buf * ASZ;
        uint32_t bb2 = b_addr + buf * BSZ;
#pragma unroll
        for (int kk = 0; kk < 2; kk++) {
            uint32_t af[4][4], bfr[4][2];
#pragma unroll
            for (int i = 0; i < 4; i++) {
                uint32_t ad = ab + (i * 16 * AKS + kk * 16) * 2;
                ldsm_x4(ad, af[i][0], af[i][1], af[i][2], af[i][3]);
            }
#pragma unroll
            for (int j = 0; j < 2; j++) {
                uint32_t bd = bb2 + (kk * 16 * BNS + j * 16) * 2;
                uint32_t r0, r1, r2, r3;
                ldsm_x4t(bd, r0, r1, r2, r3);
                bfr[j * 2][0] = r0; bfr[j * 2][1] = r1;
                bfr[j * 2 + 1][0] = r2; bfr[j * 2 + 1][1] = r3;
            }
#pragma unroll
            for (int i = 0; i < 4; i++)
#pragma unroll
                for (int j = 0; j < 4; j++) mma_bf16(acc[i][j], af[i], bfr[j]);
        }
        __syncthreads();
    }

    // epilogue
    int r = lane >> 2, c2 = (lane & 3) * 2;
#pragma unroll
    for (int i = 0; i < 4; i++) {
#pragma unroll
        for (int j = 0; j < 4; j++) {
            int col = bn + n_base + j * 8 + c2;
            float b0 = bias[col], b1 = bias[col + 1];
#pragma unroll
            for (int h = 0; h < 2; h++) {
                int row = bm + m_base + i * 16 + r + h * 8;
                float v0 = acc[i][j][h * 2 + 0] + b0;
                float v1 = acc[i][j][h * 2 + 1] + b1;
                if (OP == 1) {
                    v0 = 0.5f * v0 * (1.0f + erff(v0 * 0.70710678118654752f));
                    v1 = 0.5f * v1 * (1.0f + erff(v1 * 0.70710678118654752f));
                }
                int orow = row;
                if (SCAT) orow = wtok2tok(row);
                if (RES || SCAT) {
                    float2 rr = *(const float2*)(res + (size_t)orow * N + col);
                    v0 += rr.x; v1 += rr.y;
                }
                if (sizeof(OutT) == 4) {
                    float2 o = {v0, v1};
                    *(float2*)((float*)C + (size_t)orow * N + col) = o;
                } else {
                    __nv_bfloat162 o;
                    o.x = __float2bfloat16_rn(v0); o.y = __float2bfloat16_rn(v1);
                    *(__nv_bfloat162*)((bf16*)C + (size_t)orow * N + col) = o;
                }
            }
        }
    }
}

// ---------------------------------------------------------------------------
// Tensor-core window attention, split: one block per (window, head-pair).
// 128 threads / 4 warps; warp w -> head h0 + (w>>1), q-rows (w&1)*32..+31.
// Stages 64 x 192 bf16 (2 heads' q|k|v) with padded stride 200 -> 27KB smem,
// 4 CTAs/SM (vs 1 for the monolithic version).
// ---------------------------------------------------------------------------
#define QS2 200   // smem row stride (bf16): 400B, conflict-free for ldmatrix

__global__ __launch_bounds__(128) void attn_mma_kernel(const bf16* __restrict__ qkv,
                                                       const float* __restrict__ bias_table,
                                                       bf16* __restrict__ attno) {
    __shared__ bf16  sq[64 * QS2];
    __shared__ float sbt[2 * 225];
    int tid = threadIdx.x;
    int w  = blockIdx.x >> 2;
    int h0 = (blockIdx.x & 3) * 2;

    // load 64 rows x (q|k|v 64 cols each) for heads h0, h0+1
    const bf16* gsrc = qkv + (size_t)w * 64 * 768 + h0 * 32;
#pragma unroll
    for (int l = 0; l < 12; l++) {
        int idx = tid + l * 128;            // 0..1535
        int row = idx / 24, sub = idx - row * 24;
        int mat = sub >> 3, c8 = sub & 7;
        *(uint4*)(sq + row * QS2 + mat * 64 + c8 * 8) =
            *(const uint4*)(gsrc + (size_t)row * 768 + mat * 256 + c8 * 8);
    }
#pragma unroll
    for (int l = 0; l < 4; l++) {
        int i = tid + l * 128;
        if (i < 450) {
            int h = i / 225, rr = i - h * 225;
            sbt[i] = bias_table[rr * 8 + h0 + h];
        }
    }
    __syncthreads();

    int lane = tid & 31, wid = tid >> 5;
    int lh = wid >> 1, qr0 = (wid & 1) * 32;
    int head = h0 + lh;
    uint32_t sbase = (uint32_t)__cvta_generic_to_shared(sq);
    int qcol = lh * 32, kcol = 64 + lh * 32, vcol = 128 + lh * 32;

    // ---- S = Q K^T ----
    float s[2][8][4] = {};
#pragma unroll
    for (int ks = 0; ks < 2; ks++) {
        uint32_t aq[2][4];
#pragma unroll
        for (int mt = 0; mt < 2; mt++) {
            int row = qr0 + mt * 16 + (lane & 15);
            int col = qcol + ks * 16 + ((lane & 16) ? 8 : 0);
            ldsm_x4(sbase + (row * QS2 + col) * 2, aq[mt][0], aq[mt][1], aq[mt][2], aq[mt][3]);
        }
        uint32_t bk[8][2];
#pragma unroll
        for (int tg = 0; tg < 4; tg++) {
            int row = tg * 16 + (lane & 15);
            int col = kcol + ks * 16 + ((lane & 16) ? 8 : 0);
            uint32_t m0, m1, m2, m3;
            ldsm_x4(sbase + (row * QS2 + col) * 2, m0, m1, m2, m3);
            bk[tg * 2][0] = m0; bk[tg * 2][1] = m2;
            bk[tg * 2 + 1][0] = m1; bk[tg * 2 + 1][1] = m3;
        }
#pragma unroll
        for (int mt = 0; mt < 2; mt++)
#pragma unroll
            for (int j = 0; j < 8; j++) mma_bf16(s[mt][j], aq[mt], bk[j]);
    }

    // ---- scale + relative position bias ----
    const float scale = 0.17677669529663687f;
    const float* bt = sbt + lh * 225;
#pragma unroll
    for (int mt = 0; mt < 2; mt++)
#pragma unroll
        for (int j = 0; j < 8; j++)
#pragma unroll
            for (int e = 0; e < 4; e++) {
                int qi = qr0 + mt * 16 + (lane >> 2) + ((e >> 1) << 3);
                int kj = j * 8 + ((lane & 3) << 1) + (e & 1);
                int ridx = ((qi >> 3) - (kj >> 3) + 7) * 15 + (qi & 7) - (kj & 7) + 7;
                s[mt][j][e] = s[mt][j][e] * scale + bt[ridx];
            }

    // ---- softmax (rows in quads) ----
#pragma unroll
    for (int mt = 0; mt < 2; mt++)
#pragma unroll
        for (int h = 0; h < 2; h++) {
            float mx = -1e30f;
#pragma unroll
            for (int j = 0; j < 8; j++)
                mx = fmaxf(mx, fmaxf(s[mt][j][h * 2], s[mt][j][h * 2 + 1]));
            mx = fmaxf(mx, __shfl_xor_sync(0xffffffffu, mx, 1));
            mx = fmaxf(mx, __shfl_xor_sync(0xffffffffu, mx, 2));
            float sum = 0.0f;
#pragma unroll
            for (int j = 0; j < 8; j++) {
                float e0 = __expf(s[mt][j][h * 2] - mx);
                float e1 = __expf(s[mt][j][h * 2 + 1] - mx);
                s[mt][j][h * 2] = e0; s[mt][j][h * 2 + 1] = e1;
                sum += e0 + e1;
            }
            sum += __shfl_xor_sync(0xffffffffu, sum, 1);
            sum += __shfl_xor_sync(0xffffffffu, sum, 2);
            float rn = 1.0f / sum;
#pragma unroll
            for (int j = 0; j < 8; j++) { s[mt][j][h * 2] *= rn; s[mt][j][h * 2 + 1] *= rn; }
        }

    // ---- P -> bf16 A-fragments ----
    uint32_t ap[2][4][4];
#pragma unroll
    for (int mt = 0; mt < 2; mt++)
#pragma unroll
        for (int kt = 0; kt < 4; kt++) {
            __nv_bfloat162 t;
            t = __floats2bfloat162_rn(s[mt][2 * kt][0], s[mt][2 * kt][1]);         ap[mt][kt][0] = *(uint32_t*)&t;
            t = __floats2bfloat162_rn(s[mt][2 * kt][2], s[mt][2 * kt][3]);         ap[mt][kt][1] = *(uint32_t*)&t;
            t = __floats2bfloat162_rn(s[mt][2 * kt + 1][0], s[mt][2 * kt + 1][1]); ap[mt][kt][2] = *(uint32_t*)&t;
            t = __floats2bfloat162_rn(s[mt][2 * kt + 1][2], s[mt][2 * kt + 1][3]); ap[mt][kt][3] = *(uint32_t*)&t;
        }

    // ---- O = P V ----
    float o[2][4][4] = {};
#pragma unroll
    for (int kt = 0; kt < 4; kt++) {
        uint32_t bv[4][2];
#pragma unroll
        for (int ng = 0; ng < 2; ng++) {
            int row = kt * 16 + (lane & 15);
            int col = vcol + ng * 16 + ((lane & 16) ? 8 : 0);
            uint32_t r0, r1, r2, r3;
            ldsm_x4t(sbase + (row * QS2 + col) * 2, r0, r1, r2, r3);
            bv[ng * 2][0] = r0; bv[ng * 2][1] = r1;
            bv[ng * 2 + 1][0] = r2; bv[ng * 2 + 1][1] = r3;
        }
#pragma unroll
        for (int mt = 0; mt < 2; mt++)
#pragma unroll
            for (int nt = 0; nt < 4; nt++) mma_bf16(o[mt][nt], ap[mt][kt], bv[nt]);
    }

    // ---- store ----
#pragma unroll
    for (int mt = 0; mt < 2; mt++)
#pragma unroll
        for (int nt = 0; nt < 4; nt++)
#pragma unroll
            for (int h = 0; h < 2; h++) {
                int row = qr0 + mt * 16 + (lane >> 2) + h * 8;
                int col = head * 32 + nt * 8 + ((lane & 3) << 1);
                __nv_bfloat162 t = __floats2bfloat162_rn(o[mt][nt][h * 2], o[mt][nt][h * 2 + 1]);
                *(__nv_bfloat162*)(attno + (size_t)(w * 64 + row) * 256 + col) = t;
            }
}

// ---------------------------------------------------------------------------
extern "C" void kernel_launch(void* const* d_in, const int* in_sizes, int n_in,
                              void* d_out, int out_size) {
    const float* x         = (const float*)d_in[0];
    const float* n1g       = (const float*)d_in[1];
    const float* n1b       = (const float*)d_in[2];
    const float* qkv_w     = (const float*)d_in[3];
    const float* qkv_b     = (const float*)d_in[4];
    const float* bias_tab  = (const float*)d_in[5];
    const float* proj_w    = (const float*)d_in[6];
    const float* proj_b    = (const float*)d_in[7];
    const float* n2g       = (const float*)d_in[8];
    const float* n2b       = (const float*)d_in[9];
    const float* fc1_w     = (const float*)d_in[10];
    const float* fc1_b     = (const float*)d_in[11];
    const float* fc2_w     = (const float*)d_in[12];
    const float* fc2_b     = (const float*)d_in[13];
    float* out = (float*)d_out;

    void *pHln, *pQkv, *pAttn, *pX1, *pLn2, *pM1, *pWq, *pWp, *pW1, *pW2;
    cudaGetSymbolAddress(&pHln,  g_hln);
    cudaGetSymbolAddress(&pQkv,  g_qkv);
    cudaGetSymbolAddress(&pAttn, g_attn);
    cudaGetSymbolAddress(&pX1,   g_x1);
    cudaGetSymbolAddress(&pLn2,  g_ln2);
    cudaGetSymbolAddress(&pM1,   g_m1);
    cudaGetSymbolAddress(&pWq,   g_wqkv);
    cudaGetSymbolAddress(&pWp,   g_wproj);
    cudaGetSymbolAddress(&pW1,   g_wfc1);
    cudaGetSymbolAddress(&pW2,   g_wfc2);
    bf16* hln  = (bf16*)pHln;  bf16* qkv  = (bf16*)pQkv;
    bf16* attn = (bf16*)pAttn; float* x1  = (float*)pX1;
    bf16* ln2  = (bf16*)pLn2;  bf16* m1   = (bf16*)pM1;
    bf16* wq = (bf16*)pWq; bf16* wp = (bf16*)pWp;
    bf16* w1 = (bf16*)pW1; bf16* w2 = (bf16*)pW2;

    // 0. weight conversion (single launch, [K,N] bf16)
    cvt_all<<<768, 256>>>(qkv_w, proj_w, fc1_w, fc2_w, wq, wp, w1, w2);
    // 1. LN1 + shift + windowing -> hln (bf16, window-token order)
    ln_kernel<true><<<MTOK / 8, 256>>>(x, n1g, n1b, hln);
    // 2. qkv GEMM (bf16 out)
    bgemm<0, false, false, bf16><<<dim3(MTOK / 128, 6), 256>>>(
        hln, wq, qkv_b, nullptr, qkv, MTOK, 768, 256);
    // 3. tensor-core window attention (split, 4 blocks/window) -> attn (bf16)
    attn_mma_kernel<<<NWIN * 4, 128>>>(qkv, bias_tab, attn);
    // 4. proj GEMM + un-window scatter + residual -> x1 (fp32, token order)
    bgemm<0, false, true, float><<<dim3(MTOK / 128, 2), 256>>>(
        attn, wp, proj_b, x, x1, MTOK, 256, 256);
    // 5. LN2 -> ln2 (bf16)
    ln_kernel<false><<<MTOK / 8, 256>>>(x1, n2g, n2b, ln2);
    // 6. fc1 + GELU -> m1 (bf16)
    bgemm<1, false, false, bf16><<<dim3(MTOK / 128, 8), 256>>>(
        ln2, w1, fc1_b, nullptr, m1, MTOK, 1024, 256);
    // 7. fc2 + residual -> out (fp32)
    bgemm<0, true, false, float><<<dim3(MTOK / 128, 2), 256>>>(
        m1, w2, fc2_b, x1, out, MTOK, 256, 1024);
}

// round 11
// speedup vs baseline: 1.2562x; 1.0146x over previous
#include <cuda_runtime.h>
#include <cuda_bf16.h>
#include <math.h>
#include <stdint.h>

// ---------------------------------------------------------------------------
// SwinTransformerBlock: B=4, H=W=192, C=256, HEADS=8, HD=32, WIN=8, SHIFT=4,
// HID=1024.  M = 4*192*192 = 147456 token rows.
// ---------------------------------------------------------------------------
#define MTOK   147456
#define NWIN   2304
#define HIDD   1024

typedef __nv_bfloat16 bf16;

// -------------------- scratch (device globals; no allocation) --------------
__device__ bf16  g_hln [MTOK * 256];
__device__ bf16  g_qkv [MTOK * 768];
__device__ bf16  g_attn[MTOK * 256];
__device__ float g_x1  [MTOK * 256];
__device__ bf16  g_ln2 [MTOK * 256];
__device__ bf16  g_m1  [MTOK * 1024];
__device__ bf16  g_wqkv[256 * 768];
__device__ bf16  g_wproj[256 * 256];
__device__ bf16  g_wfc1[256 * 1024];
__device__ bf16  g_wfc2[1024 * 256];

// ---------------------------------------------------------------------------
// One launch converting all four weight matrices fp32 -> bf16 ([K,N] layout).
// ---------------------------------------------------------------------------
__global__ __launch_bounds__(256) void cvt_all(const float* __restrict__ w0,
                                               const float* __restrict__ w1,
                                               const float* __restrict__ w2,
                                               const float* __restrict__ w3,
                                               bf16* d0, bf16* d1, bf16* d2, bf16* d3) {
    int i = blockIdx.x * 256 + threadIdx.x;
    const float* s; bf16* d; int off;
    if (i < 49152)       { s = w0; d = d0; off = i; }
    else if (i < 65536)  { s = w1; d = d1; off = i - 49152; }
    else if (i < 131072) { s = w2; d = d2; off = i - 65536; }
    else                 { s = w3; d = d3; off = i - 131072; }
    float4 v = ((const float4*)s)[off];
    bf16 o[4] = {__float2bfloat16_rn(v.x), __float2bfloat16_rn(v.y),
                 __float2bfloat16_rn(v.z), __float2bfloat16_rn(v.w)};
    *(uint64_t*)(d + off * 4) = *(uint64_t*)o;
}

// ---------------------------------------------------------------------------
// LayerNorm, warp per token, bf16 output.  GATHER=true applies cyclic shift +
// window reorder (dst is window-token order).
// ---------------------------------------------------------------------------
template<bool GATHER>
__global__ __launch_bounds__(256) void ln_kernel(const float* __restrict__ x,
                                                 const float* __restrict__ g,
                                                 const float* __restrict__ bb,
                                                 bf16* __restrict__ out) {
    int warp = (blockIdx.x * 256 + threadIdx.x) >> 5;
    int lane = threadIdx.x & 31;
    int src;
    if (GATHER) {
        int w = warp >> 6, t = warp & 63;
        int b = w / 576, rem = w - b * 576;
        int wh = rem / 24, ww = rem - wh * 24;
        int r = (wh << 3) + (t >> 3) + 4; if (r >= 192) r -= 192;
        int c = (ww << 3) + (t & 7) + 4;  if (c >= 192) c -= 192;
        src = (b * 192 + r) * 192 + c;
    } else {
        src = warp;
    }
    const float4* xp = (const float4*)x + (size_t)src * 64 + lane * 2;
    float4 v0 = xp[0], v1 = xp[1];
    float s = v0.x + v0.y + v0.z + v0.w + v1.x + v1.y + v1.z + v1.w;
#pragma unroll
    for (int o = 16; o; o >>= 1) s += __shfl_xor_sync(0xffffffffu, s, o);
    float mean = s * (1.0f / 256.0f);
    float q =
        (v0.x - mean) * (v0.x - mean) + (v0.y - mean) * (v0.y - mean) +
        (v0.z - mean) * (v0.z - mean) + (v0.w - mean) * (v0.w - mean) +
        (v1.x - mean) * (v1.x - mean) + (v1.y - mean) * (v1.y - mean) +
        (v1.z - mean) * (v1.z - mean) + (v1.w - mean) * (v1.w - mean);
#pragma unroll
    for (int o = 16; o; o >>= 1) q += __shfl_xor_sync(0xffffffffu, q, o);
    float inv = rsqrtf(q * (1.0f / 256.0f) + 1e-5f);

    const float4* gp = (const float4*)g  + lane * 2;
    const float4* bp = (const float4*)bb + lane * 2;
    float4 g0 = gp[0], g1 = gp[1], b0 = bp[0], b1 = bp[1];
    bf16 o8[8];
    o8[0] = __float2bfloat16_rn((v0.x - mean) * inv * g0.x + b0.x);
    o8[1] = __float2bfloat16_rn((v0.y - mean) * inv * g0.y + b0.y);
    o8[2] = __float2bfloat16_rn((v0.z - mean) * inv * g0.z + b0.z);
    o8[3] = __float2bfloat16_rn((v0.w - mean) * inv * g0.w + b0.w);
    o8[4] = __float2bfloat16_rn((v1.x - mean) * inv * g1.x + b1.x);
    o8[5] = __float2bfloat16_rn((v1.y - mean) * inv * g1.y + b1.y);
    o8[6] = __float2bfloat16_rn((v1.z - mean) * inv * g1.z + b1.z);
    o8[7] = __float2bfloat16_rn((v1.w - mean) * inv * g1.w + b1.w);
    *(uint4*)(out + (size_t)warp * 256 + lane * 8) = *(uint4*)o8;
}

// ---------------------------------------------------------------------------
// primitives
// ---------------------------------------------------------------------------
__device__ __forceinline__ void ldsm_x4(uint32_t a, uint32_t& r0, uint32_t& r1,
                                        uint32_t& r2, uint32_t& r3) {
    asm volatile("ldmatrix.sync.aligned.m8n8.x4.shared.b16 {%0,%1,%2,%3}, [%4];\n"
                 : "=r"(r0), "=r"(r1), "=r"(r2), "=r"(r3) : "r"(a));
}
__device__ __forceinline__ void ldsm_x4t(uint32_t a, uint32_t& r0, uint32_t& r1,
                                         uint32_t& r2, uint32_t& r3) {
    asm volatile("ldmatrix.sync.aligned.m8n8.x4.trans.shared.b16 {%0,%1,%2,%3}, [%4];\n"
                 : "=r"(r0), "=r"(r1), "=r"(r2), "=r"(r3) : "r"(a));
}
__device__ __forceinline__ void mma_bf16(float* c, const uint32_t* a, const uint32_t* b) {
    asm volatile("mma.sync.aligned.m16n8k16.row.col.f32.bf16.bf16.f32 "
                 "{%0,%1,%2,%3}, {%4,%5,%6,%7}, {%8,%9}, {%0,%1,%2,%3};\n"
                 : "+f"(c[0]), "+f"(c[1]), "+f"(c[2]), "+f"(c[3])
                 : "r"(a[0]), "r"(a[1]), "r"(a[2]), "r"(a[3]), "r"(b[0]), "r"(b[1]));
}
__device__ __forceinline__ void cpasync16(uint32_t dst, const void* src) {
    asm volatile("cp.async.ca.shared.global [%0], [%1], 16;\n" :: "r"(dst), "l"(src));
}
__device__ __forceinline__ void cpcommit() {
    asm volatile("cp.async.commit_group;\n");
}

// window-token row -> flat token index (inverse shift + un-window)
__device__ __forceinline__ int wtok2tok(int row) {
    int w = row >> 6, t = row & 63;
    int b = w / 576, rem = w - b * 576;
    int wh = rem / 24, ww = rem - wh * 24;
    int r = (wh << 3) + (t >> 3) + 4; if (r >= 192) r -= 192;
    int c = (ww << 3) + (t & 7) + 4;  if (c >= 192) c -= 192;
    return (b * 192 + r) * 192 + c;
}

// ---------------------------------------------------------------------------
// bf16 tensor-core GEMM, cp.async 2-stage pipeline.
// GRID: blockIdx.x = N-column (slow A change), blockIdx.y = M-tile, so a
// resident wave shares A tiles across all N-columns via L2.
// BM=BN=128, BK=32, 256 threads, warp computes 64x32 via 4x4 m16n8k16 mma.
// OP: 0 = none, 1 = exact GELU.  SCAT: window->token scatter + residual.
// ---------------------------------------------------------------------------
#define AKS 40     // A smem row stride (bf16)
#define BNS 136    // B smem row stride (bf16)
#define ASZ (128 * AKS * 2)   // bytes per A stage
#define BSZ (32 * BNS * 2)    // bytes per B stage

template<int OP, bool RES, bool SCAT, typename OutT>
__global__ __launch_bounds__(256) void bgemm(const bf16* __restrict__ A,
                                             const bf16* __restrict__ Bw,
                                             const float* __restrict__ bias,
                                             const float* __restrict__ res,
                                             OutT* __restrict__ C,
                                             int M, int N, int K) {
    __shared__ bf16 As[2][128 * AKS];
    __shared__ bf16 Bs[2][32 * BNS];
    int tid = threadIdx.x;
    int lane = tid & 31, wid = tid >> 5;
    int bm = blockIdx.y * 128;     // M-tile on slow axis
    int bn = blockIdx.x * 128;     // N-column on fast axis
    int m_base = (wid & 1) * 64;
    int n_base = (wid >> 1) * 32;

    int a_row0 = tid >> 2,        a_kc0 = (tid & 3) * 8;
    int a_row1 = (tid + 256) >> 2;
    int b_row0 = tid >> 4,        b_nc0 = (tid & 15) * 8;
    int b_row1 = (tid + 256) >> 4;

    const bf16* Ag0 = A + (size_t)(bm + a_row0) * K + a_kc0;
    const bf16* Ag1 = A + (size_t)(bm + a_row1) * K + a_kc0;
    const bf16* Bg0 = Bw + (size_t)b_row0 * N + bn + b_nc0;
    const bf16* Bg1 = Bw + (size_t)b_row1 * N + bn + b_nc0;

    uint32_t a_smem = (uint32_t)__cvta_generic_to_shared(&As[0][0]);
    uint32_t b_smem = (uint32_t)__cvta_generic_to_shared(&Bs[0][0]);
    uint32_t a_st0 = a_smem + (a_row0 * AKS + a_kc0) * 2;
    uint32_t a_st1 = a_smem + (a_row1 * AKS + a_kc0) * 2;
    uint32_t b_st0 = b_smem + (b_row0 * BNS + b_nc0) * 2;
    uint32_t b_st1 = b_smem + (b_row1 * BNS + b_nc0) * 2;

    int a_lrow = m_base + (lane & 15);
    int a_lcol = (lane & 16) ? 8 : 0;
    uint32_t a_addr = a_smem + (a_lrow * AKS + a_lcol) * 2;
    int b_lrow = (lane & 15);
    int b_lcol = n_base + ((lane & 16) ? 8 : 0);
    uint32_t b_addr = b_smem + (b_lrow * BNS + b_lcol) * 2;

    float acc[4][4][4] = {};
    int nsteps = K >> 5;

    cpasync16(a_st0, Ag0); cpasync16(a_st1, Ag1);
    cpasync16(b_st0, Bg0); cpasync16(b_st1, Bg1);
    cpcommit();

    for (int step = 0; step < nsteps; step++) {
        int buf = step & 1;
        if (step + 1 < nsteps) {
            int nb = buf ^ 1;
            cpasync16(a_st0 + nb * ASZ, Ag0 + (step + 1) * 32);
            cpasync16(a_st1 + nb * ASZ, Ag1 + (step + 1) * 32);
            cpasync16(b_st0 + nb * BSZ, Bg0 + (size_t)(step + 1) * 32 * N);
            cpasync16(b_st1 + nb * BSZ, Bg1 + (size_t)(step + 1) * 32 * N);
            cpcommit();
            asm volatile("cp.async.wait_group 1;\n");
        } else {
            asm volatile("cp.async.wait_group 0;\n");
        }
        __syncthreads();
        uint32_t ab = a_addr + buf * ASZ;
        uint32_t bb2 = b_addr + buf * BSZ;
#pragma unroll
        for (int kk = 0; kk < 2; kk++) {
            uint32_t af[4][4], bfr[4][2];
#pragma unroll
            for (int i = 0; i < 4; i++) {
                uint32_t ad = ab + (i * 16 * AKS + kk * 16) * 2;
                ldsm_x4(ad, af[i][0], af[i][1], af[i][2], af[i][3]);
            }
#pragma unroll
            for (int j = 0; j < 2; j++) {
                uint32_t bd = bb2 + (kk * 16 * BNS + j * 16) * 2;
                uint32_t r0, r1, r2, r3;
                ldsm_x4t(bd, r0, r1, r2, r3);
                bfr[j * 2][0] = r0; bfr[j * 2][1] = r1;
                bfr[j * 2 + 1][0] = r2; bfr[j * 2 + 1][1] = r3;
            }
#pragma unroll
            for (int i = 0; i < 4; i++)
#pragma unroll
                for (int j = 0; j < 4; j++) mma_bf16(acc[i][j], af[i], bfr[j]);
        }
        __syncthreads();
    }

    // epilogue
    int r = lane >> 2, c2 = (lane & 3) * 2;
#pragma unroll
    for (int i = 0; i < 4; i++) {
#pragma unroll
        for (int j = 0; j < 4; j++) {
            int col = bn + n_base + j * 8 + c2;
            float b0 = bias[col], b1 = bias[col + 1];
#pragma unroll
            for (int h = 0; h < 2; h++) {
                int row = bm + m_base + i * 16 + r + h * 8;
                float v0 = acc[i][j][h * 2 + 0] + b0;
                float v1 = acc[i][j][h * 2 + 1] + b1;
                if (OP == 1) {
                    v0 = 0.5f * v0 * (1.0f + erff(v0 * 0.70710678118654752f));
                    v1 = 0.5f * v1 * (1.0f + erff(v1 * 0.70710678118654752f));
                }
                int orow = row;
                if (SCAT) orow = wtok2tok(row);
                if (RES || SCAT) {
                    float2 rr = *(const float2*)(res + (size_t)orow * N + col);
                    v0 += rr.x; v1 += rr.y;
                }
                if (sizeof(OutT) == 4) {
                    float2 o = {v0, v1};
                    *(float2*)((float*)C + (size_t)orow * N + col) = o;
                } else {
                    __nv_bfloat162 o;
                    o.x = __float2bfloat16_rn(v0); o.y = __float2bfloat16_rn(v1);
                    *(__nv_bfloat162*)((bf16*)C + (size_t)orow * N + col) = o;
                }
            }
        }
    }
}

// ---------------------------------------------------------------------------
// Tensor-core window attention, split: one block per (window, head-pair).
// 128 threads / 4 warps; warp w -> head h0 + (w>>1), q-rows (w&1)*32..+31.
// ---------------------------------------------------------------------------
#define QS2 200   // smem row stride (bf16): 400B, conflict-free for ldmatrix

__global__ __launch_bounds__(128) void attn_mma_kernel(const bf16* __restrict__ qkv,
                                                       const float* __restrict__ bias_table,
                                                       bf16* __restrict__ attno) {
    __shared__ bf16  sq[64 * QS2];
    __shared__ float sbt[2 * 225];
    int tid = threadIdx.x;
    int w  = blockIdx.x >> 2;
    int h0 = (blockIdx.x & 3) * 2;

    const bf16* gsrc = qkv + (size_t)w * 64 * 768 + h0 * 32;
#pragma unroll
    for (int l = 0; l < 12; l++) {
        int idx = tid + l * 128;
        int row = idx / 24, sub = idx - row * 24;
        int mat = sub >> 3, c8 = sub & 7;
        *(uint4*)(sq + row * QS2 + mat * 64 + c8 * 8) =
            *(const uint4*)(gsrc + (size_t)row * 768 + mat * 256 + c8 * 8);
    }
#pragma unroll
    for (int l = 0; l < 4; l++) {
        int i = tid + l * 128;
        if (i < 450) {
            int h = i / 225, rr = i - h * 225;
            sbt[i] = bias_table[rr * 8 + h0 + h];
        }
    }
    __syncthreads();

    int lane = tid & 31, wid = tid >> 5;
    int lh = wid >> 1, qr0 = (wid & 1) * 32;
    int head = h0 + lh;
    uint32_t sbase = (uint32_t)__cvta_generic_to_shared(sq);
    int qcol = lh * 32, kcol = 64 + lh * 32, vcol = 128 + lh * 32;

    float s[2][8][4] = {};
#pragma unroll
    for (int ks = 0; ks < 2; ks++) {
        uint32_t aq[2][4];
#pragma unroll
        for (int mt = 0; mt < 2; mt++) {
            int row = qr0 + mt * 16 + (lane & 15);
            int col = qcol + ks * 16 + ((lane & 16) ? 8 : 0);
            ldsm_x4(sbase + (row * QS2 + col) * 2, aq[mt][0], aq[mt][1], aq[mt][2], aq[mt][3]);
        }
        uint32_t bk[8][2];
#pragma unroll
        for (int tg = 0; tg < 4; tg++) {
            int row = tg * 16 + (lane & 15);
            int col = kcol + ks * 16 + ((lane & 16) ? 8 : 0);
            uint32_t m0, m1, m2, m3;
            ldsm_x4(sbase + (row * QS2 + col) * 2, m0, m1, m2, m3);
            bk[tg * 2][0] = m0; bk[tg * 2][1] = m2;
            bk[tg * 2 + 1][0] = m1; bk[tg * 2 + 1][1] = m3;
        }
#pragma unroll
        for (int mt = 0; mt < 2; mt++)
#pragma unroll
            for (int j = 0; j < 8; j++) mma_bf16(s[mt][j], aq[mt], bk[j]);
    }

    const float scale = 0.17677669529663687f;
    const float* bt = sbt + lh * 225;
#pragma unroll
    for (int mt = 0; mt < 2; mt++)
#pragma unroll
        for (int j = 0; j < 8; j++)
#pragma unroll
            for (int e = 0; e < 4; e++) {
                int qi = qr0 + mt * 16 + (lane >> 2) + ((e >> 1) << 3);
                int kj = j * 8 + ((lane & 3) << 1) + (e & 1);
                int ridx = ((qi >> 3) - (kj >> 3) + 7) * 15 + (qi & 7) - (kj & 7) + 7;
                s[mt][j][e] = s[mt][j][e] * scale + bt[ridx];
            }

#pragma unroll
    for (int mt = 0; mt < 2; mt++)
#pragma unroll
        for (int h = 0; h < 2; h++) {
            float mx = -1e30f;
#pragma unroll
            for (int j = 0; j < 8; j++)
                mx = fmaxf(mx, fmaxf(s[mt][j][h * 2], s[mt][j][h * 2 + 1]));
            mx = fmaxf(mx, __shfl_xor_sync(0xffffffffu, mx, 1));
            mx = fmaxf(mx, __shfl_xor_sync(0xffffffffu, mx, 2));
            float sum = 0.0f;
#pragma unroll
            for (int j = 0; j < 8; j++) {
                float e0 = __expf(s[mt][j][h * 2] - mx);
                float e1 = __expf(s[mt][j][h * 2 + 1] - mx);
                s[mt][j][h * 2] = e0; s[mt][j][h * 2 + 1] = e1;
                sum += e0 + e1;
            }
            sum += __shfl_xor_sync(0xffffffffu, sum, 1);
            sum += __shfl_xor_sync(0xffffffffu, sum, 2);
            float rn = 1.0f / sum;
#pragma unroll
            for (int j = 0; j < 8; j++) { s[mt][j][h * 2] *= rn; s[mt][j][h * 2 + 1] *= rn; }
        }

    uint32_t ap[2][4][4];
#pragma unroll
    for (int mt = 0; mt < 2; mt++)
#pragma unroll
        for (int kt = 0; kt < 4; kt++) {
            __nv_bfloat162 t;
            t = __floats2bfloat162_rn(s[mt][2 * kt][0], s[mt][2 * kt][1]);         ap[mt][kt][0] = *(uint32_t*)&t;
            t = __floats2bfloat162_rn(s[mt][2 * kt][2], s[mt][2 * kt][3]);         ap[mt][kt][1] = *(uint32_t*)&t;
            t = __floats2bfloat162_rn(s[mt][2 * kt + 1][0], s[mt][2 * kt + 1][1]); ap[mt][kt][2] = *(uint32_t*)&t;
            t = __floats2bfloat162_rn(s[mt][2 * kt + 1][2], s[mt][2 * kt + 1][3]); ap[mt][kt][3] = *(uint32_t*)&t;
        }

    float o[2][4][4] = {};
#pragma unroll
    for (int kt = 0; kt < 4; kt++) {
        uint32_t bv[4][2];
#pragma unroll
        for (int ng = 0; ng < 2; ng++) {
            int row = kt * 16 + (lane & 15);
            int col = vcol + ng * 16 + ((lane & 16) ? 8 : 0);
            uint32_t r0, r1, r2, r3;
            ldsm_x4t(sbase + (row * QS2 + col) * 2, r0, r1, r2, r3);
            bv[ng * 2][0] = r0; bv[ng * 2][1] = r1;
            bv[ng * 2 + 1][0] = r2; bv[ng * 2 + 1][1] = r3;
        }
#pragma unroll
        for (int mt = 0; mt < 2; mt++)
#pragma unroll
            for (int nt = 0; nt < 4; nt++) mma_bf16(o[mt][nt], ap[mt][kt], bv[nt]);
    }

#pragma unroll
    for (int mt = 0; mt < 2; mt++)
#pragma unroll
        for (int nt = 0; nt < 4; nt++)
#pragma unroll
            for (int h = 0; h < 2; h++) {
                int row = qr0 + mt * 16 + (lane >> 2) + h * 8;
                int col = head * 32 + nt * 8 + ((lane & 3) << 1);
                __nv_bfloat162 t = __floats2bfloat162_rn(o[mt][nt][h * 2], o[mt][nt][h * 2 + 1]);
                *(__nv_bfloat162*)(attno + (size_t)(w * 64 + row) * 256 + col) = t;
            }
}

// ---------------------------------------------------------------------------
extern "C" void kernel_launch(void* const* d_in, const int* in_sizes, int n_in,
                              void* d_out, int out_size) {
    const float* x         = (const float*)d_in[0];
    const float* n1g       = (const float*)d_in[1];
    const float* n1b       = (const float*)d_in[2];
    const float* qkv_w     = (const float*)d_in[3];
    const float* qkv_b     = (const float*)d_in[4];
    const float* bias_tab  = (const float*)d_in[5];
    const float* proj_w    = (const float*)d_in[6];
    const float* proj_b    = (const float*)d_in[7];
    const float* n2g       = (const float*)d_in[8];
    const float* n2b       = (const float*)d_in[9];
    const float* fc1_w     = (const float*)d_in[10];
    const float* fc1_b     = (const float*)d_in[11];
    const float* fc2_w     = (const float*)d_in[12];
    const float* fc2_b     = (const float*)d_in[13];
    float* out = (float*)d_out;

    void *pHln, *pQkv, *pAttn, *pX1, *pLn2, *pM1, *pWq, *pWp, *pW1, *pW2;
    cudaGetSymbolAddress(&pHln,  g_hln);
    cudaGetSymbolAddress(&pQkv,  g_qkv);
    cudaGetSymbolAddress(&pAttn, g_attn);
    cudaGetSymbolAddress(&pX1,   g_x1);
    cudaGetSymbolAddress(&pLn2,  g_ln2);
    cudaGetSymbolAddress(&pM1,   g_m1);
    cudaGetSymbolAddress(&pWq,   g_wqkv);
    cudaGetSymbolAddress(&pWp,   g_wproj);
    cudaGetSymbolAddress(&pW1,   g_wfc1);
    cudaGetSymbolAddress(&pW2,   g_wfc2);
    bf16* hln  = (bf16*)pHln;  bf16* qkv  = (bf16*)pQkv;
    bf16* attn = (bf16*)pAttn; float* x1  = (float*)pX1;
    bf16* ln2  = (bf16*)pLn2;  bf16* m1   = (bf16*)pM1;
    bf16* wq = (bf16*)pWq; bf16* wp = (bf16*)pWp;
    bf16* w1 = (bf16*)pW1; bf16* w2 = (bf16*)pW2;

    // 0. weight conversion (single launch, [K,N] bf16)
    cvt_all<<<768, 256>>>(qkv_w, proj_w, fc1_w, fc2_w, wq, wp, w1, w2);
    // 1. LN1 + shift + windowing -> hln (bf16, window-token order)
    ln_kernel<true><<<MTOK / 8, 256>>>(x, n1g, n1b, hln);
    // 2. qkv GEMM (bf16 out) — grid (Ncols, Mtiles) for L2 A-reuse
    bgemm<0, false, false, bf16><<<dim3(6, MTOK / 128), 256>>>(
        hln, wq, qkv_b, nullptr, qkv, MTOK, 768, 256);
    // 3. tensor-core window attention (split, 4 blocks/window) -> attn (bf16)
    attn_mma_kernel<<<NWIN * 4, 128>>>(qkv, bias_tab, attn);
    // 4. proj GEMM + un-window scatter + residual -> x1 (fp32, token order)
    bgemm<0, false, true, float><<<dim3(2, MTOK / 128), 256>>>(
        attn, wp, proj_b, x, x1, MTOK, 256, 256);
    // 5. LN2 -> ln2 (bf16)
    ln_kernel<false><<<MTOK / 8, 256>>>(x1, n2g, n2b, ln2);
    // 6. fc1 + GELU -> m1 (bf16)
    bgemm<1, false, false, bf16><<<dim3(8, MTOK / 128), 256>>>(
        ln2, w1, fc1_b, nullptr, m1, MTOK, 1024, 256);
    // 7. fc2 + residual -> out (fp32)
    bgemm<0, true, false, float><<<dim3(2, MTOK / 128), 256>>>(
        m1, w2, fc2_b, x1, out, MTOK, 256, 1024);
}